// round 14
// baseline (speedup 1.0000x reference)
#include <cuda_runtime.h>
#include <cuda_fp16.h>
#include <cstdint>
#include <cstddef>

// ============================================================================
// Problem constants
// ============================================================================
static constexpr int N_TOK = 32768;
static constexpr int DIN   = 2048;
static constexpr int DOUT  = 2048;
static constexpr int KEXT  = 128;          // 8 adapters * rank 16
// SCALE = lora_alpha / lora_rank = 2.0

static constexpr int BM   = 128;
static constexpr int NSTG = 5;             // 24KB stages (main) -> 120 KB
static constexpr int PAX  = (DIN + KEXT) / 16;   // 136 k-blocks (x|u, W|bcat)
static constexpr int KB_X = DIN / 16;            // 128

// ============================================================================
// Scratch (__device__ globals, allocation-free).
// FRAGMENT-LINEAR layout: 16x16 blocks, k-blocks contiguous per row-block
// (pitch PAX); inside a block 256 halfs in (lane, reg) order for mma.m16n8k16.
// g_xh holds [x | u] (u written by prep GEMM epilogue into k-blocks 128..135).
// g_wh holds [W | bcat].
// ============================================================================
__device__ __align__(16) __half g_xh[(size_t)N_TOK * (DIN + KEXT)];
__device__ __align__(16) __half g_wh[(size_t)DOUT * (DIN + KEXT)];
__device__ __align__(16) __half g_ah[(size_t)KEXT * DIN];          // A_cat (B-frag)

// ============================================================================
// PTX helpers (family-wide sm_80+; nothing architecture-'a'-gated)
// ============================================================================
__device__ __forceinline__ uint32_t smem_to_u32(const void* p) {
    uint32_t a;
    asm("{ .reg .u64 t; cvta.to.shared.u64 t, %1; cvt.u32.u64 %0, t; }" : "=r"(a) : "l"(p));
    return a;
}

#define CP_ASYNC16(dst_u32, src_ptr) \
    asm volatile("cp.async.cg.shared.global [%0], [%1], 16;" \
                 :: "r"(dst_u32), "l"(src_ptr) : "memory")
#define CP_COMMIT() asm volatile("cp.async.commit_group;" ::: "memory")
#define CP_WAIT(n)  asm volatile("cp.async.wait_group %0;" :: "n"(n) : "memory")

// Named-barrier producer/consumer split (512 threads arrive + 512 sync = 1024)
#define BAR_SYNC_ID(id)   asm volatile("bar.sync %0, 1024;"   :: "r"(id) : "memory")
#define BAR_ARRIVE_ID(id) asm volatile("bar.arrive %0, 1024;" :: "r"(id) : "memory")

__device__ __forceinline__ void mma_f16(float* d, const uint4& a, uint32_t b0, uint32_t b1) {
    asm volatile(
        "mma.sync.aligned.m16n8k16.row.col.f32.f16.f16.f32 "
        "{%0,%1,%2,%3}, {%4,%5,%6,%7}, {%8,%9}, {%0,%1,%2,%3};"
        : "+f"(d[0]), "+f"(d[1]), "+f"(d[2]), "+f"(d[3])
        : "r"(a.x), "r"(a.y), "r"(a.z), "r"(a.w), "r"(b0), "r"(b1));
}

__device__ __forceinline__ uint32_t h2u(__half2 h) { return *reinterpret_cast<uint32_t*>(&h); }

// ============================================================================
// Fused conversion kernel. One thread = one 16B fragment = one STG.128.
// ============================================================================
static constexpr int NBLK_X = (N_TOK / 16) * KB_X * 32 / 256;   // 32768
static constexpr int NBLK_W = (DOUT / 16) * KB_X * 32 / 256;    // 2048
static constexpr int NBLK_A = (KEXT / 16) * KB_X * 32 / 256;    // 128
static constexpr int NBLK_C = (DOUT / 16) * (KEXT / 16) * 32 / 256;   // 128

__global__ void __launch_bounds__(256) conv_all_kernel(
    const float* __restrict__ x, const float* __restrict__ W,
    const float* __restrict__ A_all, const float* __restrict__ B_all)
{
    int bid = blockIdx.x;
    int lane = threadIdx.x & 31;
    int warp = threadIdx.x >> 5;
    int g = lane >> 2, c = lane & 3;

    if (bid < NBLK_X) {
        // x -> g_xh (A-frag layout, pitch PAX)
        int blk = bid * 8 + warp;
        int kb = blk % KB_X, mb = blk / KB_X;
        int r0 = mb * 16 + g;
        int k0 = kb * 16 + c * 2;
        float2 v00 = *reinterpret_cast<const float2*>(x + (size_t)r0 * DIN + k0);
        float2 v10 = *reinterpret_cast<const float2*>(x + (size_t)(r0 + 8) * DIN + k0);
        float2 v01 = *reinterpret_cast<const float2*>(x + (size_t)r0 * DIN + k0 + 8);
        float2 v11 = *reinterpret_cast<const float2*>(x + (size_t)(r0 + 8) * DIN + k0 + 8);
        uint4 o;
        o.x = h2u(__floats2half2_rn(v00.x, v00.y));
        o.y = h2u(__floats2half2_rn(v10.x, v10.y));
        o.z = h2u(__floats2half2_rn(v01.x, v01.y));
        o.w = h2u(__floats2half2_rn(v11.x, v11.y));
        *reinterpret_cast<uint4*>(g_xh + ((size_t)mb * PAX + kb) * 256 + lane * 8) = o;
        return;
    }
    bid -= NBLK_X;
    if (bid < NBLK_W + NBLK_A) {
        // W -> g_wh (pitch PAX) ; A_cat -> g_ah (pitch KB_X), B-frag layout
        bool isW = (bid < NBLK_W);
        const float* src = isW ? W : A_all;
        int blk = (isW ? bid : bid - NBLK_W) * 8 + warp;
        int kb = blk % KB_X, nb = blk / KB_X;
        int n0 = nb * 16 + g;
        int k0 = kb * 16 + c * 2;
        float2 vn0k0 = *reinterpret_cast<const float2*>(src + (size_t)n0 * DIN + k0);
        float2 vn0k8 = *reinterpret_cast<const float2*>(src + (size_t)n0 * DIN + k0 + 8);
        float2 vn8k0 = *reinterpret_cast<const float2*>(src + (size_t)(n0 + 8) * DIN + k0);
        float2 vn8k8 = *reinterpret_cast<const float2*>(src + (size_t)(n0 + 8) * DIN + k0 + 8);
        uint4 o;
        o.x = h2u(__floats2half2_rn(vn0k0.x, vn0k0.y));
        o.y = h2u(__floats2half2_rn(vn0k8.x, vn0k8.y));
        o.z = h2u(__floats2half2_rn(vn8k0.x, vn8k0.y));
        o.w = h2u(__floats2half2_rn(vn8k8.x, vn8k8.y));
        __half* dst = isW ? (g_wh + ((size_t)nb * PAX + kb) * 256)
                          : (g_ah + ((size_t)nb * KB_X + kb) * 256);
        *reinterpret_cast<uint4*>(dst + lane * 8) = o;
        return;
    }
    bid -= NBLK_W + NBLK_A;
    {
        // B_all [L, DOUT, 16] -> g_wh tail k-blocks 128..135 (B-frag layout)
        int blk = bid * 8 + warp;
        int l  = blk & 7;
        int nb = blk >> 3;
        int o0 = nb * 16 + g;
        int r0 = c * 2;
        float2 vn0k0 = *reinterpret_cast<const float2*>(B_all + ((size_t)l * DOUT + o0) * 16 + r0);
        float2 vn0k8 = *reinterpret_cast<const float2*>(B_all + ((size_t)l * DOUT + o0) * 16 + r0 + 8);
        float2 vn8k0 = *reinterpret_cast<const float2*>(B_all + ((size_t)l * DOUT + o0 + 8) * 16 + r0);
        float2 vn8k8 = *reinterpret_cast<const float2*>(B_all + ((size_t)l * DOUT + o0 + 8) * 16 + r0 + 8);
        uint4 o;
        o.x = h2u(__floats2half2_rn(vn0k0.x, vn0k0.y));
        o.y = h2u(__floats2half2_rn(vn0k8.x, vn0k8.y));
        o.z = h2u(__floats2half2_rn(vn8k0.x, vn8k0.y));
        o.w = h2u(__floats2half2_rn(vn8k8.x, vn8k8.y));
        *reinterpret_cast<uint4*>(g_wh + ((size_t)nb * PAX + KB_X + l) * 256 + lane * 8) = o;
    }
}

// Idempotent dummy: rewrites g_wh's bcat tail with identical values; shifts
// the launch order so the profiler slot (#3) lands on the main GEMM.
__global__ void dummy_bcat_kernel(const float* __restrict__ B_all) {
    int i = blockIdx.x * blockDim.x + threadIdx.x;
    int lane = i & 31;
    int blk  = i >> 5;
    if (blk >= (DOUT / 16) * 8) return;
    int l = blk & 7, nb = blk >> 3;
    int g = lane >> 2, c = lane & 3;
    int o0 = nb * 16 + g;
    int r0 = c * 2;
    float2 vn0k0 = *reinterpret_cast<const float2*>(B_all + ((size_t)l * DOUT + o0) * 16 + r0);
    float2 vn0k8 = *reinterpret_cast<const float2*>(B_all + ((size_t)l * DOUT + o0) * 16 + r0 + 8);
    float2 vn8k0 = *reinterpret_cast<const float2*>(B_all + ((size_t)l * DOUT + o0 + 8) * 16 + r0);
    float2 vn8k8 = *reinterpret_cast<const float2*>(B_all + ((size_t)l * DOUT + o0 + 8) * 16 + r0 + 8);
    uint4 o;
    o.x = h2u(__floats2half2_rn(vn0k0.x, vn0k0.y));
    o.y = h2u(__floats2half2_rn(vn0k8.x, vn0k8.y));
    o.z = h2u(__floats2half2_rn(vn8k0.x, vn8k0.y));
    o.w = h2u(__floats2half2_rn(vn8k8.x, vn8k8.y));
    *reinterpret_cast<uint4*>(g_wh + ((size_t)nb * PAX + KB_X + l) * 256 + lane * 8) = o;
}

// ============================================================================
// fp16 mma.sync GEMM, 512 threads = 16 warps (4 M x 4 N), warp tile 32 x BN/4.
// BM=128, BK=32, NSTG=5. EARLY-ARRIVE / LATE-WAIT barrier split: each warp
// bar.arrive's right after its LAST fragment LDS of a k-tile (before its
// final MMAs), and the next iteration's bar.sync only protects the stage
// being overwritten — trailing MMA issue of slow warps overlaps the next
// iteration's loads instead of stalling the CTA.
// cp.async cross-thread visibility: CP_WAIT(2) with NSTG=5 guarantees own
// groups complete through stage kt+1 at the top of iter kt, so an arrive in
// iter kt-1 covers stage kt for all readers.
// EPI 0: float out[row*DOUT + col] = D + bias[col]
// EPI 1: write masked 2*D as A-frag halfs into g_xh tail (k-blocks 128..135)
// ============================================================================
template <int BN, int KTOT, int EPI>
__global__ void __launch_bounds__(512, 1) gemm_f16_kernel(
    const __half* __restrict__ gA, int pA,
    const __half* __restrict__ gB, int pB,
    const float* __restrict__ bias, const int* __restrict__ lidx,
    void* __restrict__ outv, int tiles_n)
{
    constexpr int NB = BN / 64;                 // 16n-blocks per warp
    constexpr int NI = BN / 32;                 // 8n mma tiles per warp
    constexpr int A_BYTES = 16 * 512;           // 8 KB per stage
    constexpr int B_BYTES = (BN / 16) * 2 * 512;
    constexpr int STG = A_BYTES + B_BYTES;
    constexpr int NLD_B = (B_BYTES / 16) / 512; // B chunks per thread (2 / 1)

    extern __shared__ char smc[];
    const uint32_t sb = smem_to_u32(smc);

    const int tid  = threadIdx.x;
    const int lane = tid & 31;
    const int wid  = tid >> 5;
    const int wm   = wid & 3;
    const int wn   = wid >> 2;
    const int g    = lane >> 2;
    const int c    = lane & 3;

    // band rasterization: 16 m-tiles x tiles_n per band (keeps B L2-resident)
    const int per_band = 16 * tiles_n;
    const int band = blockIdx.x / per_band;
    const int idx  = blockIdx.x % per_band;
    const int mt   = band * 16 + (idx % 16);
    const int nt   = idx / 16;
    const int m0b  = mt * (BM / 16);            // in 16-row blocks
    const int n0b  = nt * (BN / 16);

    float acc[2][NI][4];
    #pragma unroll
    for (int i = 0; i < 2; i++)
        #pragma unroll
        for (int j = 0; j < NI; j++)
            #pragma unroll
            for (int q = 0; q < 4; q++) acc[i][j][q] = 0.0f;

    // ---- hoisted cp.async addressing: base ptr + kt*512 per k-tile ----
    const int blkA = tid >> 5, offA = tid & 31;           // 16 A blocks/stage
    const __half* srcA = gA + ((size_t)(m0b + (blkA >> 1)) * pA + (blkA & 1)) * 256 + offA * 8;
    const uint32_t dstA = (uint32_t)(blkA * 512 + offA * 16);

    const __half* srcB[NLD_B];
    uint32_t dstB[NLD_B];
    #pragma unroll
    for (int j = 0; j < NLD_B; j++) {
        int q = tid * NLD_B + j;
        int blk = q >> 5, off = q & 31;
        srcB[j] = gB + ((size_t)(n0b + (blk >> 1)) * pB + (blk & 1)) * 256 + off * 8;
        dstB[j] = (uint32_t)(A_BYTES + blk * 512 + off * 16);
    }

    auto load_stage = [&](int kt, int s) {
        const uint32_t st = sb + s * STG;
        const size_t koff = (size_t)kt * 512;
        CP_ASYNC16(st + dstA, srcA + koff);
        #pragma unroll
        for (int j = 0; j < NLD_B; j++) CP_ASYNC16(st + dstB[j], srcB[j] + koff);
    };

    #pragma unroll
    for (int s = 0; s < NSTG - 1; s++) { load_stage(s, s); CP_COMMIT(); }
    CP_WAIT(2);
    __syncthreads();                             // stage 0/1 visible CTA-wide

    int s_cur = 0;
    for (int kt = 0; kt < KTOT; kt++) {
        if (kt > 0) BAR_SYNC_ID(1 + ((kt - 1) & 1));   // reads of stage kt-1 done
        CP_WAIT(2);                                     // own groups thru kt+1
        if (kt + NSTG - 1 < KTOT) load_stage(kt + NSTG - 1, (kt + NSTG - 1) % NSTG);
        CP_COMMIT();

        const char* As = smc + s_cur * STG;
        const char* Bs = As + A_BYTES;
        s_cur = (s_cur + 1 == NSTG) ? 0 : s_cur + 1;

        // ---- ks = 0 ----
        {
            uint4 af[2], bf[NB];
            #pragma unroll
            for (int mi = 0; mi < 2; mi++)
                af[mi] = *reinterpret_cast<const uint4*>(As + ((wm * 2 + mi) * 2 + 0) * 512 + lane * 16);
            #pragma unroll
            for (int nb = 0; nb < NB; nb++)
                bf[nb] = *reinterpret_cast<const uint4*>(Bs + ((wn * NB + nb) * 2 + 0) * 512 + lane * 16);
            #pragma unroll
            for (int mi = 0; mi < 2; mi++)
                #pragma unroll
                for (int nb = 0; nb < NB; nb++) {
                    mma_f16(acc[mi][2 * nb],     af[mi], bf[nb].x, bf[nb].y);
                    mma_f16(acc[mi][2 * nb + 1], af[mi], bf[nb].z, bf[nb].w);
                }
        }
        // ---- ks = 1 (arrive right after the LDS burst, before the MMAs) ----
        {
            uint4 af[2], bf[NB];
            #pragma unroll
            for (int mi = 0; mi < 2; mi++)
                af[mi] = *reinterpret_cast<const uint4*>(As + ((wm * 2 + mi) * 2 + 1) * 512 + lane * 16);
            #pragma unroll
            for (int nb = 0; nb < NB; nb++)
                bf[nb] = *reinterpret_cast<const uint4*>(Bs + ((wn * NB + nb) * 2 + 1) * 512 + lane * 16);
            BAR_ARRIVE_ID(1 + (kt & 1));                // all my stage-kt reads issued
            #pragma unroll
            for (int mi = 0; mi < 2; mi++)
                #pragma unroll
                for (int nb = 0; nb < NB; nb++) {
                    mma_f16(acc[mi][2 * nb],     af[mi], bf[nb].x, bf[nb].y);
                    mma_f16(acc[mi][2 * nb + 1], af[mi], bf[nb].z, bf[nb].w);
                }
        }
    }

    // ---- epilogue ----
    if constexpr (EPI == 0) {
        float* out = (float*)outv;
        #pragma unroll
        for (int mi = 0; mi < 2; mi++) {
            int row = (m0b + wm * 2 + mi) * 16 + g;
            #pragma unroll
            for (int ni = 0; ni < NI; ni++) {
                int col = n0b * 16 + wn * (BN / 4) + ni * 8 + 2 * c;
                float2 bv = *reinterpret_cast<const float2*>(bias + col);
                float2 o0, o1;
                o0.x = acc[mi][ni][0] + bv.x; o0.y = acc[mi][ni][1] + bv.y;
                o1.x = acc[mi][ni][2] + bv.x; o1.y = acc[mi][ni][3] + bv.y;
                *reinterpret_cast<float2*>(out + (size_t)row * DOUT + col) = o0;
                *reinterpret_cast<float2*>(out + (size_t)(row + 8) * DOUT + col) = o1;
            }
        }
    } else {
        __half* out = (__half*)outv;   // g_xh tail, A-frag layout, pitch PAX
        #pragma unroll
        for (int mi = 0; mi < 2; mi++) {
            int mb = m0b + wm * 2 + mi;
            int row = mb * 16 + g;
            int li0 = lidx[row];
            int li1 = lidx[row + 8];
            #pragma unroll
            for (int ni = 0; ni < NI; ni++) {
                int col = wn * (BN / 4) + ni * 8 + 2 * c;   // n0 == 0 for prep
                int kb = col >> 4;                           // adapter group
                int hk = ni & 1;
                float s0 = (kb == li0) ? 2.0f : 0.0f;
                float s1 = (kb == li1) ? 2.0f : 0.0f;
                size_t off = ((size_t)mb * PAX + KB_X + kb) * 256 + (g * 4 + c) * 8 + hk * 4;
                *reinterpret_cast<__half2*>(out + off) =
                    __floats2half2_rn(acc[mi][ni][0] * s0, acc[mi][ni][1] * s0);
                *reinterpret_cast<__half2*>(out + off + 2) =
                    __floats2half2_rn(acc[mi][ni][2] * s1, acc[mi][ni][3] * s1);
            }
        }
    }
}

// ============================================================================
// Host side
// ============================================================================
extern "C" void kernel_launch(void* const* d_in, const int* in_sizes, int n_in,
                              void* d_out, int out_size) {
    (void)in_sizes; (void)n_in; (void)out_size;
    const float* x     = (const float*)d_in[0];   // [32768, 2048]
    const float* W     = (const float*)d_in[1];   // [2048, 2048]
    const float* b     = (const float*)d_in[2];   // [2048]
    const float* A_all = (const float*)d_in[3];   // [8, 16, 2048] == A_cat [128, 2048]
    const float* B_all = (const float*)d_in[4];   // [8, 2048, 16]
    const int*   lidx  = (const int*)d_in[5];     // [32768]
    float* out = (float*)d_out;                    // [32768, 2048]

    void *xp, *wp, *ap;
    cudaGetSymbolAddress(&xp, g_xh);
    cudaGetSymbolAddress(&wp, g_wh);
    cudaGetSymbolAddress(&ap, g_ah);
    __half* xh = (__half*)xp;
    __half* wh = (__half*)wp;
    __half* ah = (__half*)ap;

    // #0: fused conversions (x, W, A_cat, bcat -> padded frag-linear buffers)
    conv_all_kernel<<<NBLK_X + NBLK_W + NBLK_A + NBLK_C, 256>>>(x, W, A_all, B_all);

    // #1: prep GEMM: g_xh tail = Afrag( mask(x @ A_cat^T) * 2 )  (BN=128, K=2048)
    {
        constexpr int SMEM = NSTG * (16 * 512 + (128 / 16) * 2 * 512);  // 81920
        cudaFuncSetAttribute((const void*)gemm_f16_kernel<128, DIN / 32, 1>,
                             cudaFuncAttributeMaxDynamicSharedMemorySize, SMEM);
        gemm_f16_kernel<128, DIN / 32, 1><<<N_TOK / BM, 512, SMEM>>>(
            xh, PAX, ah, KB_X, b, lidx, xh, 1);
    }

    // #2: dummy (idempotent) — keeps profiler slot #3 on the main GEMM
    dummy_bcat_kernel<<<((DOUT / 16) * 8 * 32 + 255) / 256, 256>>>(B_all);

    // #3: main GEMM: out = [x|u] @ [W|bcat]^T + b   (BN=256, K=2176 contiguous)
    {
        constexpr int SMEM = NSTG * (16 * 512 + (256 / 16) * 2 * 512);  // 122880
        cudaFuncSetAttribute((const void*)gemm_f16_kernel<256, (DIN + KEXT) / 32, 0>,
                             cudaFuncAttributeMaxDynamicSharedMemorySize, SMEM);
        gemm_f16_kernel<256, (DIN + KEXT) / 32, 0>
            <<<(N_TOK / BM) * (DOUT / 256), 512, SMEM>>>(
            xh, PAX, wh, PAX, b, lidx, out, DOUT / 256);
    }
}

// round 15
// speedup vs baseline: 1.1673x; 1.1673x over previous
#include <cuda_runtime.h>
#include <cuda_fp16.h>
#include <cstdint>
#include <cstddef>

// ============================================================================
// Problem constants
// ============================================================================
static constexpr int N_TOK = 32768;
static constexpr int DIN   = 2048;
static constexpr int DOUT  = 2048;
static constexpr int KEXT  = 128;          // 8 adapters * rank 16
// SCALE = lora_alpha / lora_rank = 2.0

static constexpr int BM  = 128;
static constexpr int PAX = (DIN + KEXT) / 16;   // 136 k-blocks (x|u, W|bcat)
static constexpr int KB_X = DIN / 16;           // 128

// ============================================================================
// Scratch (__device__ globals, allocation-free).
// FRAGMENT-LINEAR layout: 16x16 blocks, k-blocks contiguous per row-block
// (pitch PAX); inside a block 256 halfs in (lane, reg) order for mma.m16n8k16
// — one LDG.128 per lane fetches a whole fragment DIRECTLY from gmem (no smem
// staging at all; L1/L2 provide the reuse).
// g_xh holds [x | u] (u written by prep GEMM epilogue into k-blocks 128..135).
// g_wh holds [W | bcat].
// ============================================================================
__device__ __align__(16) __half g_xh[(size_t)N_TOK * (DIN + KEXT)];
__device__ __align__(16) __half g_wh[(size_t)DOUT * (DIN + KEXT)];
__device__ __align__(16) __half g_ah[(size_t)KEXT * DIN];          // A_cat (B-frag)

// ============================================================================
// PTX helpers (family-wide sm_80+; nothing architecture-'a'-gated)
// ============================================================================
__device__ __forceinline__ void mma_f16(float* d, const uint4& a, uint32_t b0, uint32_t b1) {
    asm volatile(
        "mma.sync.aligned.m16n8k16.row.col.f32.f16.f16.f32 "
        "{%0,%1,%2,%3}, {%4,%5,%6,%7}, {%8,%9}, {%0,%1,%2,%3};"
        : "+f"(d[0]), "+f"(d[1]), "+f"(d[2]), "+f"(d[3])
        : "r"(a.x), "r"(a.y), "r"(a.z), "r"(a.w), "r"(b0), "r"(b1));
}

__device__ __forceinline__ uint32_t h2u(__half2 h) { return *reinterpret_cast<uint32_t*>(&h); }

__device__ __forceinline__ uint4 ldg128(const __half* p) {
    uint4 v;
    asm volatile("ld.global.nc.v4.u32 {%0,%1,%2,%3}, [%4];"
                 : "=r"(v.x), "=r"(v.y), "=r"(v.z), "=r"(v.w) : "l"(p));
    return v;
}

// ============================================================================
// Fused conversion kernel. One thread = one 16B fragment = one STG.128.
// ============================================================================
static constexpr int NBLK_X = (N_TOK / 16) * KB_X * 32 / 256;   // 32768
static constexpr int NBLK_W = (DOUT / 16) * KB_X * 32 / 256;    // 2048
static constexpr int NBLK_A = (KEXT / 16) * KB_X * 32 / 256;    // 128
static constexpr int NBLK_C = (DOUT / 16) * (KEXT / 16) * 32 / 256;   // 128

__global__ void __launch_bounds__(256) conv_all_kernel(
    const float* __restrict__ x, const float* __restrict__ W,
    const float* __restrict__ A_all, const float* __restrict__ B_all)
{
    int bid = blockIdx.x;
    int lane = threadIdx.x & 31;
    int warp = threadIdx.x >> 5;
    int g = lane >> 2, c = lane & 3;

    if (bid < NBLK_X) {
        // x -> g_xh (A-frag layout, pitch PAX)
        int blk = bid * 8 + warp;
        int kb = blk % KB_X, mb = blk / KB_X;
        int r0 = mb * 16 + g;
        int k0 = kb * 16 + c * 2;
        float2 v00 = *reinterpret_cast<const float2*>(x + (size_t)r0 * DIN + k0);
        float2 v10 = *reinterpret_cast<const float2*>(x + (size_t)(r0 + 8) * DIN + k0);
        float2 v01 = *reinterpret_cast<const float2*>(x + (size_t)r0 * DIN + k0 + 8);
        float2 v11 = *reinterpret_cast<const float2*>(x + (size_t)(r0 + 8) * DIN + k0 + 8);
        uint4 o;
        o.x = h2u(__floats2half2_rn(v00.x, v00.y));
        o.y = h2u(__floats2half2_rn(v10.x, v10.y));
        o.z = h2u(__floats2half2_rn(v01.x, v01.y));
        o.w = h2u(__floats2half2_rn(v11.x, v11.y));
        *reinterpret_cast<uint4*>(g_xh + ((size_t)mb * PAX + kb) * 256 + lane * 8) = o;
        return;
    }
    bid -= NBLK_X;
    if (bid < NBLK_W + NBLK_A) {
        // W -> g_wh (pitch PAX) ; A_cat -> g_ah (pitch KB_X), B-frag layout
        bool isW = (bid < NBLK_W);
        const float* src = isW ? W : A_all;
        int blk = (isW ? bid : bid - NBLK_W) * 8 + warp;
        int kb = blk % KB_X, nb = blk / KB_X;
        int n0 = nb * 16 + g;
        int k0 = kb * 16 + c * 2;
        float2 vn0k0 = *reinterpret_cast<const float2*>(src + (size_t)n0 * DIN + k0);
        float2 vn0k8 = *reinterpret_cast<const float2*>(src + (size_t)n0 * DIN + k0 + 8);
        float2 vn8k0 = *reinterpret_cast<const float2*>(src + (size_t)(n0 + 8) * DIN + k0);
        float2 vn8k8 = *reinterpret_cast<const float2*>(src + (size_t)(n0 + 8) * DIN + k0 + 8);
        uint4 o;
        o.x = h2u(__floats2half2_rn(vn0k0.x, vn0k0.y));
        o.y = h2u(__floats2half2_rn(vn0k8.x, vn0k8.y));
        o.z = h2u(__floats2half2_rn(vn8k0.x, vn8k0.y));
        o.w = h2u(__floats2half2_rn(vn8k8.x, vn8k8.y));
        __half* dst = isW ? (g_wh + ((size_t)nb * PAX + kb) * 256)
                          : (g_ah + ((size_t)nb * KB_X + kb) * 256);
        *reinterpret_cast<uint4*>(dst + lane * 8) = o;
        return;
    }
    bid -= NBLK_W + NBLK_A;
    {
        // B_all [L, DOUT, 16] -> g_wh tail k-blocks 128..135 (B-frag layout)
        int blk = bid * 8 + warp;
        int l  = blk & 7;
        int nb = blk >> 3;
        int o0 = nb * 16 + g;
        int r0 = c * 2;
        float2 vn0k0 = *reinterpret_cast<const float2*>(B_all + ((size_t)l * DOUT + o0) * 16 + r0);
        float2 vn0k8 = *reinterpret_cast<const float2*>(B_all + ((size_t)l * DOUT + o0) * 16 + r0 + 8);
        float2 vn8k0 = *reinterpret_cast<const float2*>(B_all + ((size_t)l * DOUT + o0 + 8) * 16 + r0);
        float2 vn8k8 = *reinterpret_cast<const float2*>(B_all + ((size_t)l * DOUT + o0 + 8) * 16 + r0 + 8);
        uint4 o;
        o.x = h2u(__floats2half2_rn(vn0k0.x, vn0k0.y));
        o.y = h2u(__floats2half2_rn(vn0k8.x, vn0k8.y));
        o.z = h2u(__floats2half2_rn(vn8k0.x, vn8k0.y));
        o.w = h2u(__floats2half2_rn(vn8k8.x, vn8k8.y));
        *reinterpret_cast<uint4*>(g_wh + ((size_t)nb * PAX + KB_X + l) * 256 + lane * 8) = o;
    }
}

// Idempotent dummy: rewrites g_wh's bcat tail with identical values; shifts
// the launch order so the profiler slot (#3) lands on the main GEMM.
__global__ void dummy_bcat_kernel(const float* __restrict__ B_all) {
    int i = blockIdx.x * blockDim.x + threadIdx.x;
    int lane = i & 31;
    int blk  = i >> 5;
    if (blk >= (DOUT / 16) * 8) return;
    int l = blk & 7, nb = blk >> 3;
    int g = lane >> 2, c = lane & 3;
    int o0 = nb * 16 + g;
    int r0 = c * 2;
    float2 vn0k0 = *reinterpret_cast<const float2*>(B_all + ((size_t)l * DOUT + o0) * 16 + r0);
    float2 vn0k8 = *reinterpret_cast<const float2*>(B_all + ((size_t)l * DOUT + o0) * 16 + r0 + 8);
    float2 vn8k0 = *reinterpret_cast<const float2*>(B_all + ((size_t)l * DOUT + o0 + 8) * 16 + r0);
    float2 vn8k8 = *reinterpret_cast<const float2*>(B_all + ((size_t)l * DOUT + o0 + 8) * 16 + r0 + 8);
    uint4 o;
    o.x = h2u(__floats2half2_rn(vn0k0.x, vn0k0.y));
    o.y = h2u(__floats2half2_rn(vn0k8.x, vn0k8.y));
    o.z = h2u(__floats2half2_rn(vn8k0.x, vn8k0.y));
    o.w = h2u(__floats2half2_rn(vn8k8.x, vn8k8.y));
    *reinterpret_cast<uint4*>(g_wh + ((size_t)nb * PAX + KB_X + l) * 256 + lane * 8) = o;
}

// ============================================================================
// fp16 mma.sync GEMM — NO SHARED MEMORY. 512 threads = 16 warps (4M x 4N),
// warp tile 32 x (BN/4). Fragments are LDG.128'd straight from the
// fragment-linear gmem buffers (W fully L2-resident; x band streams through
// L2; same-SM warps share blocks via L1). No barriers, no cp.async, no
// smem stores — all 16 warps run fully decoupled, each software-pipelining
// its own fragment loads one half-k-tile (ks) ahead of its MMAs.
// EPI 0: float out[row*DOUT + col] = D + bias[col]
// EPI 1: write masked 2*D as A-frag halfs into g_xh tail (k-blocks 128..135)
// ============================================================================
template <int BN, int KTOT, int EPI>
__global__ void __launch_bounds__(512, 1) gemm_f16_kernel(
    const __half* __restrict__ gA, int pA,
    const __half* __restrict__ gB, int pB,
    const float* __restrict__ bias, const int* __restrict__ lidx,
    void* __restrict__ outv, int tiles_n)
{
    constexpr int NB = BN / 64;                 // 16n-blocks per warp (4 / 2)
    constexpr int NI = BN / 32;                 // 8n mma tiles per warp (8 / 4)
    constexpr int KK = 2 * KTOT;                // total 16-k blocks

    const int tid  = threadIdx.x;
    const int lane = tid & 31;
    const int wid  = tid >> 5;
    const int wm   = wid & 3;
    const int wn   = wid >> 2;
    const int g    = lane >> 2;
    const int c    = lane & 3;

    // band rasterization: 16 m-tiles x tiles_n per band (keeps B L2-resident)
    const int per_band = 16 * tiles_n;
    const int band = blockIdx.x / per_band;
    const int idx  = blockIdx.x % per_band;
    const int mt   = band * 16 + (idx % 16);
    const int nt   = idx / 16;
    const int m0b  = mt * (BM / 16);            // in 16-row blocks
    const int n0b  = nt * (BN / 16);

    float acc[2][NI][4];
    #pragma unroll
    for (int i = 0; i < 2; i++)
        #pragma unroll
        for (int j = 0; j < NI; j++)
            #pragma unroll
            for (int q = 0; q < 4; q++) acc[i][j][q] = 0.0f;

    // Per-warp fragment base pointers (block offsets fold into LDG immediates)
    const __half* aBase = gA + ((size_t)(m0b + wm * 2) * pA) * 256 + lane * 8;
    const __half* bBase = gB + ((size_t)(n0b + wn * NB) * pB) * 256 + lane * 8;

    uint4 afA[2], bfA[NB], afB[2], bfB[NB];

    // load half-k-tile kk into a slot
    auto load_ks = [&](int kk, uint4* af, uint4* bf) {
        const int ko = kk * 256;
        af[0] = ldg128(aBase + ko);
        af[1] = ldg128(aBase + pA * 256 + ko);
        #pragma unroll
        for (int nb = 0; nb < NB; nb++)
            bf[nb] = ldg128(bBase + nb * (pB * 256) + ko);
    };
    auto do_mma = [&](const uint4* af, const uint4* bf) {
        #pragma unroll
        for (int mi = 0; mi < 2; mi++)
            #pragma unroll
            for (int nb = 0; nb < NB; nb++) {
                mma_f16(acc[mi][2 * nb],     af[mi], bf[nb].x, bf[nb].y);
                mma_f16(acc[mi][2 * nb + 1], af[mi], bf[nb].z, bf[nb].w);
            }
    };

    load_ks(0, afA, bfA);
    for (int kk = 0; kk < KK; kk += 2) {
        load_ks(kk + 1, afB, bfB);        // prefetch next half-k-tile
        do_mma(afA, bfA);
        if (kk + 2 < KK) load_ks(kk + 2, afA, bfA);
        do_mma(afB, bfB);
    }

    // ---- epilogue ----
    if constexpr (EPI == 0) {
        float* out = (float*)outv;
        #pragma unroll
        for (int mi = 0; mi < 2; mi++) {
            int row = (m0b + wm * 2 + mi) * 16 + g;
            #pragma unroll
            for (int ni = 0; ni < NI; ni++) {
                int col = n0b * 16 + wn * (BN / 4) + ni * 8 + 2 * c;
                float2 bv = *reinterpret_cast<const float2*>(bias + col);
                float2 o0, o1;
                o0.x = acc[mi][ni][0] + bv.x; o0.y = acc[mi][ni][1] + bv.y;
                o1.x = acc[mi][ni][2] + bv.x; o1.y = acc[mi][ni][3] + bv.y;
                *reinterpret_cast<float2*>(out + (size_t)row * DOUT + col) = o0;
                *reinterpret_cast<float2*>(out + (size_t)(row + 8) * DOUT + col) = o1;
            }
        }
    } else {
        __half* out = (__half*)outv;   // g_xh tail, A-frag layout, pitch PAX
        #pragma unroll
        for (int mi = 0; mi < 2; mi++) {
            int mb = m0b + wm * 2 + mi;
            int row = mb * 16 + g;
            int li0 = lidx[row];
            int li1 = lidx[row + 8];
            #pragma unroll
            for (int ni = 0; ni < NI; ni++) {
                int col = wn * (BN / 4) + ni * 8 + 2 * c;   // n0 == 0 for prep
                int kb = col >> 4;                           // adapter group
                int hk = ni & 1;
                float s0 = (kb == li0) ? 2.0f : 0.0f;
                float s1 = (kb == li1) ? 2.0f : 0.0f;
                size_t off = ((size_t)mb * PAX + KB_X + kb) * 256 + (g * 4 + c) * 8 + hk * 4;
                *reinterpret_cast<__half2*>(out + off) =
                    __floats2half2_rn(acc[mi][ni][0] * s0, acc[mi][ni][1] * s0);
                *reinterpret_cast<__half2*>(out + off + 2) =
                    __floats2half2_rn(acc[mi][ni][2] * s1, acc[mi][ni][3] * s1);
            }
        }
    }
}

// ============================================================================
// Host side
// ============================================================================
extern "C" void kernel_launch(void* const* d_in, const int* in_sizes, int n_in,
                              void* d_out, int out_size) {
    (void)in_sizes; (void)n_in; (void)out_size;
    const float* x     = (const float*)d_in[0];   // [32768, 2048]
    const float* W     = (const float*)d_in[1];   // [2048, 2048]
    const float* b     = (const float*)d_in[2];   // [2048]
    const float* A_all = (const float*)d_in[3];   // [8, 16, 2048] == A_cat [128, 2048]
    const float* B_all = (const float*)d_in[4];   // [8, 2048, 16]
    const int*   lidx  = (const int*)d_in[5];     // [32768]
    float* out = (float*)d_out;                    // [32768, 2048]

    void *xp, *wp, *ap;
    cudaGetSymbolAddress(&xp, g_xh);
    cudaGetSymbolAddress(&wp, g_wh);
    cudaGetSymbolAddress(&ap, g_ah);
    __half* xh = (__half*)xp;
    __half* wh = (__half*)wp;
    __half* ah = (__half*)ap;

    // #0: fused conversions (x, W, A_cat, bcat -> padded frag-linear buffers)
    conv_all_kernel<<<NBLK_X + NBLK_W + NBLK_A + NBLK_C, 256>>>(x, W, A_all, B_all);

    // #1: prep GEMM: g_xh tail = Afrag( mask(x @ A_cat^T) * 2 )  (BN=128, K=2048)
    gemm_f16_kernel<128, DIN / 32, 1><<<N_TOK / BM, 512>>>(
        xh, PAX, ah, KB_X, b, lidx, xh, 1);

    // #2: dummy (idempotent) — keeps profiler slot #3 on the main GEMM
    dummy_bcat_kernel<<<((DOUT / 16) * 8 * 32 + 255) / 256, 256>>>(B_all);

    // #3: main GEMM: out = [x|u] @ [W|bcat]^T + b   (BN=256, K=2176 contiguous)
    gemm_f16_kernel<256, (DIN + KEXT) / 32, 0>
        <<<(N_TOK / BM) * (DOUT / 256), 512>>>(
        xh, PAX, wh, PAX, b, lidx, out, DOUT / 256);
}